// round 5
// baseline (speedup 1.0000x reference)
#include <cuda_runtime.h>
#include <cstdint>

#define B 64
#define K 8
#define V 128000
#define NCH 64
#define CH 2000           // V / NCH
#define PLACEHOLDER_F (-1.0f)

// scratch (no allocations allowed); zero-init at module load
__device__ float g_csum[B * NCH];
__device__ float g_cmax[B * NCH];
__device__ int   g_camax[B * NCH];
__device__ int   g_cnt[B];

// ---------------------------------------------------------------------------
// Single fused kernel: grid (NCH, B), 256 threads.
//   prologue: every block recomputes accept/na/j for its batch (L2-hot after wave 1)
//   body:     chunk residual sum + chunk max/argmax of target row
//   c==0:     writes all static output fields
//   last block per batch: cumsum over chunks, threshold search, re-read crossing
//             chunk (L2-hot), write recovered token, reset counter
// ---------------------------------------------------------------------------
__global__ void __launch_bounds__(256) k_fused(const int* __restrict__ dtok,
                                               const float* __restrict__ dp,
                                               const float* __restrict__ tp,
                                               const int* __restrict__ bonus,
                                               const float* __restrict__ us,
                                               float* __restrict__ out) {
    int c = blockIdx.x;          // chunk 0..63
    int b = blockIdx.y;          // batch 0..63
    int t = threadIdx.x;         // 256

    __shared__ int s_acc[K];
    __shared__ int s_na, s_j;

    // ---- prologue: accept bits -> na, j ----
    if (t < K) {
        int tok = dtok[b * K + t];
        size_t off = (size_t)(b * K + t) * V + (size_t)tok;
        float p = __ldg(tp + off);
        float q = __ldg(dp + off);
        float ap = fminf(1.0f, p / fmaxf(q, 1e-10f));
        s_acc[t] = (us[b * K + t] < ap) ? 1 : 0;
    }
    __syncthreads();
    if (t == 0) {
        int na = 0;
        for (int i = 0; i < K; i++) { if (s_acc[i]) na++; else break; }
        s_na = na;
        s_j = (na < K) ? na : (K - 1);
    }
    __syncthreads();
    int na = s_na;
    int j  = s_j;

    // ---- streaming body: chunk sum + max/argmax of target ----
    size_t base = ((size_t)(b * K + j)) * V + (size_t)c * CH;
    const float4* t4 = (const float4*)(tp + base);
    const float4* d4 = (const float4*)(dp + base);

    float s = 0.0f;
    float mx = -1.0f;
    int   mi = V;
    const int N4 = CH / 4;       // 500
    for (int i = t; i < N4; i += 256) {
        float4 tv = t4[i];
        float4 dv = d4[i];
        s += fmaxf(tv.x - dv.x, 0.0f);
        s += fmaxf(tv.y - dv.y, 0.0f);
        s += fmaxf(tv.z - dv.z, 0.0f);
        s += fmaxf(tv.w - dv.w, 0.0f);
        int gi = c * CH + i * 4;
        if (tv.x > mx) { mx = tv.x; mi = gi; }
        if (tv.y > mx) { mx = tv.y; mi = gi + 1; }
        if (tv.z > mx) { mx = tv.z; mi = gi + 2; }
        if (tv.w > mx) { mx = tv.w; mi = gi + 3; }
    }

    __shared__ float ssum[256];
    __shared__ float smax[256];
    __shared__ int   sidx[256];
    ssum[t] = s; smax[t] = mx; sidx[t] = mi;
    __syncthreads();
    for (int st = 128; st > 0; st >>= 1) {
        if (t < st) {
            ssum[t] += ssum[t + st];
            float ov = smax[t + st]; int oi = sidx[t + st];
            if (ov > smax[t] || (ov == smax[t] && oi < sidx[t])) {
                smax[t] = ov; sidx[t] = oi;
            }
        }
        __syncthreads();
    }
    if (t == 0) {
        g_csum[b * NCH + c]  = ssum[0];
        g_cmax[b * NCH + c]  = smax[0];
        g_camax[b * NCH + c] = sidx[0];
    }

    // ---- static output fields (chunk-0 block) ----
    if (c == 0 && t == 0) {
        bool all = (na == K);
        for (int pos = 0; pos <= K; pos++) {
            if (pos < na) {
                out[b * (K + 1) + pos] = (float)dtok[b * K + pos];
            } else if (pos == na) {
                if (all) out[b * (K + 1) + pos] = (float)bonus[b];
                // else: finalizer writes the recovered token here
            } else {
                out[b * (K + 1) + pos] = PLACEHOLDER_F;
            }
        }
        int ob = B * (K + 1);
        out[ob + b]         = (float)na;          // num_accepted
        out[ob + B + b]     = (float)na;          // accepted_counts
        out[ob + 2 * B + b] = (na == K) ? 0.0f : 1.0f;  // recovered_counts
        out[ob + 3 * B + b] = (na == K) ? 1.0f : 0.0f;  // bonus_counts
    }

    // ---- last-block election ----
    __shared__ int s_last;
    if (t == 0) {
        __threadfence();
        int old = atomicAdd(&g_cnt[b], 1);
        s_last = (old == NCH - 1) ? 1 : 0;
    }
    __syncthreads();
    if (!s_last) return;

    // ---- finalize (one block per batch) ----
    __shared__ float cum[NCH];
    __shared__ float thr_s, pref_s, total_s;
    __shared__ int   cidx, fb_amax, cand;
    __shared__ float segsum[256];
    __shared__ float segex[256];

    if (t == 0) {
        g_cnt[b] = 0;   // reset for next graph replay
        float run = 0.0f;
        for (int ci = 0; ci < NCH; ci++) { run += g_csum[b * NCH + ci]; cum[ci] = run; }
        total_s = run;
        float thr = us[b * K + j] * run;
        thr_s = thr;
        int cc = NCH - 1;
        for (int i = 0; i < NCH; i++) if (cum[i] > thr) { cc = i; break; }
        cidx = cc;
        pref_s = (cc > 0) ? cum[cc - 1] : 0.0f;
        float fmx = -1.0f; int fmi = V;
        for (int ci = 0; ci < NCH; ci++) {
            float v = g_cmax[b * NCH + ci];
            int id  = g_camax[b * NCH + ci];
            if (v > fmx || (v == fmx && id < fmi)) { fmx = v; fmi = id; }
        }
        fb_amax = fmi;
        cand = V - 1;   // safety default (measure-zero boundary rounding)
    }
    __syncthreads();

    int cc = cidx;
    size_t fbase = ((size_t)(b * K + j)) * V + (size_t)cc * CH;

    float rv[8];
    float ls = 0.0f;
    int s0 = t * 8;
    if (s0 < CH) {
        #pragma unroll
        for (int e = 0; e < 8; e++) {
            int ii = s0 + e;
            float r = (ii < CH) ? fmaxf(tp[fbase + ii] - dp[fbase + ii], 0.0f) : 0.0f;
            rv[e] = r; ls += r;
        }
    }
    segsum[t] = (s0 < CH) ? ls : 0.0f;
    __syncthreads();
    if (t == 0) {
        float run = pref_s;
        for (int i = 0; i < 256; i++) { segex[i] = run; run += segsum[i]; }
    }
    __syncthreads();

    if (s0 < CH) {
        float run = segex[t];
        float thr = thr_s;
        #pragma unroll
        for (int e = 0; e < 8; e++) {
            int ii = s0 + e;
            if (ii >= CH) break;
            run += rv[e];
            if (run > thr) { atomicMin(&cand, cc * CH + ii); break; }
        }
    }
    __syncthreads();

    if (t == 0) {
        int rec = (total_s > 0.0f) ? cand : fb_amax;
        if (na < K) out[b * (K + 1) + na] = (float)rec;
    }
}

// ---------------------------------------------------------------------------
extern "C" void kernel_launch(void* const* d_in, const int* in_sizes, int n_in,
                              void* d_out, int out_size) {
    const int*   dtok  = (const int*)d_in[0];   // [B,K]
    const float* dp    = (const float*)d_in[1]; // [B,K,V] draft probs
    const float* tp    = (const float*)d_in[2]; // [B,K,V] target probs
    const int*   bonus = (const int*)d_in[3];   // [B]
    const float* us    = (const float*)d_in[4]; // [B,K]
    float* out = (float*)d_out;

    dim3 g(NCH, B);
    k_fused<<<g, 256>>>(dtok, dp, tp, bonus, us, out);
}

// round 6
// speedup vs baseline: 1.6810x; 1.6810x over previous
#include <cuda_runtime.h>
#include <cstdint>

#define B 64
#define K 8
#define V 128000
#define NCH 64
#define CH 2000           // V / NCH
#define PLACEHOLDER_F (-1.0f)

// scratch (no allocations allowed)
__device__ int   g_acc[B * K];
__device__ float g_csum[B * NCH];
__device__ float g_cmax[B * NCH];
__device__ int   g_camax[B * NCH];

// ---------------------------------------------------------------------------
// Kernel 1: 512 blocks, one (b,k) gather each -> latency overlapped across SMs
// ---------------------------------------------------------------------------
__global__ void k1_accept(const int* __restrict__ dtok,
                          const float* __restrict__ dp,
                          const float* __restrict__ tp,
                          const float* __restrict__ us) {
    int i = blockIdx.x;                  // 0 .. B*K-1
    if (threadIdx.x == 0) {
        int tok = dtok[i];
        size_t off = (size_t)i * V + (size_t)tok;
        float p = __ldg(tp + off);
        float q = __ldg(dp + off);
        float ap = fminf(1.0f, p / fmaxf(q, 1e-10f));
        g_acc[i] = (us[i] < ap) ? 1 : 0;
    }
}

// ---------------------------------------------------------------------------
// Kernel 2: grid (NCH, B), 256 thr. Streams the j-row, per-chunk sum+max/argmax.
//           c==0 block also writes all static output fields.
// ---------------------------------------------------------------------------
__global__ void __launch_bounds__(256) k2_chunks(const int* __restrict__ dtok,
                                                 const float* __restrict__ dp,
                                                 const float* __restrict__ tp,
                                                 const int* __restrict__ bonus,
                                                 float* __restrict__ out) {
    int c = blockIdx.x;          // chunk 0..63
    int b = blockIdx.y;          // batch 0..63
    int t = threadIdx.x;         // 256

    __shared__ int s_acc[K];
    __shared__ int s_na;
    if (t < K) s_acc[t] = g_acc[b * K + t];   // one L2-hot line
    __syncthreads();
    if (t == 0) {
        int na = 0;
        for (int i = 0; i < K; i++) { if (s_acc[i]) na++; else break; }
        s_na = na;
    }
    __syncthreads();
    int na = s_na;
    int j  = (na < K) ? na : (K - 1);

    size_t base = ((size_t)(b * K + j)) * V + (size_t)c * CH;
    const float4* t4 = (const float4*)(tp + base);
    const float4* d4 = (const float4*)(dp + base);

    float s = 0.0f;
    float mx = -1.0f;
    int   mi = V;
    const int N4 = CH / 4;       // 500
    for (int i = t; i < N4; i += 256) {
        float4 tv = t4[i];
        float4 dv = d4[i];
        s += fmaxf(tv.x - dv.x, 0.0f);
        s += fmaxf(tv.y - dv.y, 0.0f);
        s += fmaxf(tv.z - dv.z, 0.0f);
        s += fmaxf(tv.w - dv.w, 0.0f);
        int gi = c * CH + i * 4;
        // strict > keeps first occurrence within the (increasing) thread walk
        if (tv.x > mx) { mx = tv.x; mi = gi; }
        if (tv.y > mx) { mx = tv.y; mi = gi + 1; }
        if (tv.z > mx) { mx = tv.z; mi = gi + 2; }
        if (tv.w > mx) { mx = tv.w; mi = gi + 3; }
    }

    __shared__ float ssum[256];
    __shared__ float smax[256];
    __shared__ int   sidx[256];
    ssum[t] = s; smax[t] = mx; sidx[t] = mi;
    __syncthreads();
    for (int st = 128; st > 0; st >>= 1) {
        if (t < st) {
            ssum[t] += ssum[t + st];
            float ov = smax[t + st]; int oi = sidx[t + st];
            if (ov > smax[t] || (ov == smax[t] && oi < sidx[t])) {
                smax[t] = ov; sidx[t] = oi;
            }
        }
        __syncthreads();
    }
    if (t == 0) {
        g_csum[b * NCH + c]  = ssum[0];
        g_cmax[b * NCH + c]  = smax[0];
        g_camax[b * NCH + c] = sidx[0];
    }

    // static output fields (chunk-0 block only)
    if (c == 0 && t == 0) {
        bool all = (na == K);
        for (int pos = 0; pos <= K; pos++) {
            if (pos < na) {
                out[b * (K + 1) + pos] = (float)dtok[b * K + pos];
            } else if (pos == na) {
                if (all) out[b * (K + 1) + pos] = (float)bonus[b];
                // else: k3 writes the recovered token here
            } else {
                out[b * (K + 1) + pos] = PLACEHOLDER_F;
            }
        }
        int ob = B * (K + 1);
        out[ob + b]         = (float)na;               // num_accepted
        out[ob + B + b]     = (float)na;               // accepted_counts
        out[ob + 2 * B + b] = all ? 0.0f : 1.0f;       // recovered_counts
        out[ob + 3 * B + b] = all ? 1.0f : 0.0f;       // bonus_counts
    }
}

// ---------------------------------------------------------------------------
// Kernel 3: one block per batch; chunk-scan + L2-hot re-read of crossing chunk
// ---------------------------------------------------------------------------
__global__ void __launch_bounds__(256) k3_finalize(const float* __restrict__ dp,
                                                   const float* __restrict__ tp,
                                                   const float* __restrict__ us,
                                                   float* __restrict__ out) {
    int b = blockIdx.x;
    int t = threadIdx.x;   // 256

    __shared__ int s_acc[K];
    __shared__ float cum[NCH];
    __shared__ float thr_s, pref_s, total_s;
    __shared__ int   s_na, cidx, fb_amax, cand;
    __shared__ float segsum[256];
    __shared__ float segex[256];

    if (t < K) s_acc[t] = g_acc[b * K + t];
    __syncthreads();
    if (t == 0) {
        int na = 0;
        for (int i = 0; i < K; i++) { if (s_acc[i]) na++; else break; }
        s_na = na;
    }
    __syncthreads();
    int na = s_na;
    int j  = (na < K) ? na : (K - 1);

    if (t == 0) {
        float run = 0.0f;
        for (int ci = 0; ci < NCH; ci++) { run += g_csum[b * NCH + ci]; cum[ci] = run; }
        total_s = run;
        float thr = us[b * K + j] * run;
        thr_s = thr;
        int cc = NCH - 1;
        for (int i = 0; i < NCH; i++) if (cum[i] > thr) { cc = i; break; }
        cidx = cc;
        pref_s = (cc > 0) ? cum[cc - 1] : 0.0f;
        // fallback argmax(target row), first occurrence
        float fmx = -1.0f; int fmi = V;
        for (int ci = 0; ci < NCH; ci++) {
            float v = g_cmax[b * NCH + ci];
            int id  = g_camax[b * NCH + ci];
            if (v > fmx || (v == fmx && id < fmi)) { fmx = v; fmi = id; }
        }
        fb_amax = fmi;
        cand = V - 1;   // safety default (measure-zero boundary rounding)
    }
    __syncthreads();

    int cc = cidx;
    size_t fbase = ((size_t)(b * K + j)) * V + (size_t)cc * CH;

    float rv[8];
    float ls = 0.0f;
    int s0 = t * 8;
    if (s0 < CH) {
        #pragma unroll
        for (int e = 0; e < 8; e++) {
            int ii = s0 + e;
            float r = (ii < CH) ? fmaxf(tp[fbase + ii] - dp[fbase + ii], 0.0f) : 0.0f;
            rv[e] = r; ls += r;
        }
    }
    segsum[t] = (s0 < CH) ? ls : 0.0f;
    __syncthreads();
    if (t == 0) {
        float run = pref_s;
        for (int i = 0; i < 256; i++) { segex[i] = run; run += segsum[i]; }
    }
    __syncthreads();

    if (s0 < CH) {
        float run = segex[t];
        float thr = thr_s;
        #pragma unroll
        for (int e = 0; e < 8; e++) {
            int ii = s0 + e;
            if (ii >= CH) break;
            run += rv[e];
            if (run > thr) { atomicMin(&cand, cc * CH + ii); break; }
        }
    }
    __syncthreads();

    if (t == 0) {
        int rec = (total_s > 0.0f) ? cand : fb_amax;
        if (na < K) out[b * (K + 1) + na] = (float)rec;
    }
}

// ---------------------------------------------------------------------------
extern "C" void kernel_launch(void* const* d_in, const int* in_sizes, int n_in,
                              void* d_out, int out_size) {
    const int*   dtok  = (const int*)d_in[0];   // [B,K]
    const float* dp    = (const float*)d_in[1]; // [B,K,V] draft probs
    const float* tp    = (const float*)d_in[2]; // [B,K,V] target probs
    const int*   bonus = (const int*)d_in[3];   // [B]
    const float* us    = (const float*)d_in[4]; // [B,K]
    float* out = (float*)d_out;

    k1_accept<<<B * K, 32>>>(dtok, dp, tp, us);
    dim3 g2(NCH, B);
    k2_chunks<<<g2, 256>>>(dtok, dp, tp, bonus, out);
    k3_finalize<<<B, 256>>>(dp, tp, us, out);
}